// round 12
// baseline (speedup 1.0000x reference)
#include <cuda_runtime.h>
#include <cstdint>

#define BATCH 64
#define TT    2048
#define HID   128
#define G3    384
#define NPROD 84
#define NTHR  768          // 384 rows x 2 K-halves
#define NCH   ((TT + NPROD - 1) / NPROD)   // 25 chunks

// Scratch: gi[t][b][g] (201 MB) + per-chunk completion counters.
__device__ __align__(16) float g_gi[(size_t)TT * BATCH * G3];
__device__ int g_cnt[NCH];

__device__ __forceinline__ unsigned long long pack2(float lo, float hi) {
    unsigned long long r;
    asm("mov.b64 %0, {%1, %2};" : "=l"(r) : "f"(lo), "f"(hi));
    return r;
}
__device__ __forceinline__ void unpack2(unsigned long long v, float &lo, float &hi) {
    asm("mov.b64 {%0, %1}, %2;" : "=f"(lo), "=f"(hi) : "l"(v));
}
// Packed f32x2 FMA: d = a*b + d. 2x fp32 throughput on sm_103a.
__device__ __forceinline__ void ffma2(unsigned long long &d, unsigned long long a,
                                      unsigned long long b) {
    asm("fma.rn.f32x2 %0, %1, %2, %0;" : "+l"(d) : "l"(a), "l"(b));
}
__device__ __forceinline__ float sigmoidf_(float x) {
    return __fdividef(1.0f, 1.0f + __expf(-x));
}
__device__ __forceinline__ void cp_async16(uint32_t dst_smem, const void* src) {
    asm volatile("cp.async.cg.shared.global [%0], [%1], 16;"
                 :: "r"(dst_smem), "l"(src) : "memory");
}

// Every thread spins on a volatile read, then its own acquire-side fence
// (pairs with the producer's release fence through the observed atomic).
__device__ __forceinline__ void wait_chunk(int c, int target) {
    volatile int* p = (volatile int*)&g_cnt[c];
    while (*p < target) __nanosleep(64);
    __threadfence();
}

__global__ void reset_kernel() {
    int i = threadIdx.x;
    if (i < NCH) g_cnt[i] = 0;
}

__global__ void __launch_bounds__(NTHR, 1)
gru_kernel(const float* __restrict__ x,      // [B, T, 128]
           const float* __restrict__ w_ih,   // [384, 128]
           const float* __restrict__ w_hh,   // [384, 128]
           const float* __restrict__ b_ih,   // [384]
           const float* __restrict__ b_hh,   // [384]
           const float* __restrict__ w_proj, // [64, 128]
           const float* __restrict__ b_proj, // [64]
           float* __restrict__ out)          // [64, 64]
{
    __shared__ float s_x[BATCH * HID];                  // producer staging (32 KB)
    __shared__ float s_pu[384];                         // producer hi-half partials
    __shared__ float s_part[NTHR];                      // consumer GEMV partials
    __shared__ float s_h[HID];
    __shared__ alignas(16) float s_gi[2][G3];           // gi double buffer
    __shared__ float s_pool[HID];

    const int tid = threadIdx.x;
    const int hf  = (tid >= 384);          // K-half: 0 -> cols 0..63, 1 -> cols 64..127
    const int row = tid - (hf << 8) - (hf << 7);   // tid - 384*hf  (exact row 0..383)

    if (blockIdx.x >= BATCH) {
        // ============================ PRODUCER ============================
        const int w = blockIdx.x - BATCH;
        unsigned long long wr[32];
        const unsigned long long* W =
            reinterpret_cast<const unsigned long long*>(w_ih) + (size_t)row * 64 + hf * 32;
        #pragma unroll
        for (int i = 0; i < 32; i++) wr[i] = W[i];
        const unsigned long long bias = (hf == 0) ? pack2(b_ih[row], 0.0f) : pack2(0.0f, 0.0f);

        for (int c = 0; c < NCH; c++) {
            const int t = c * NPROD + w;
            if (t >= TT) break;
            for (int idx = tid; idx < BATCH * HID; idx += NTHR)
                s_x[idx] = __ldcg(&x[(((size_t)(idx >> 7)) * TT + t) * HID + (idx & 127)]);
            __syncthreads();

            float* gout = g_gi + (size_t)t * BATCH * G3;
            for (int b = 0; b < BATCH; b++) {
                const ulonglong2* hx =
                    reinterpret_cast<const ulonglong2*>(s_x + b * HID + hf * 64);
                unsigned long long a0 = bias, a1 = pack2(0.0f, 0.0f);
                #pragma unroll
                for (int i = 0; i < 16; i++) {
                    ulonglong2 v = hx[i];
                    ffma2(a0, wr[2 * i],     v.x);
                    ffma2(a1, wr[2 * i + 1], v.y);
                }
                float s0, s1, s2, s3;
                unpack2(a0, s0, s1);
                unpack2(a1, s2, s3);
                float psum = (s0 + s1) + (s2 + s3);
                if (hf) s_pu[row] = psum;
                __syncthreads();
                if (!hf) gout[b * G3 + row] = psum + s_pu[row];
                __syncthreads();
            }
            __threadfence();            // release: order gi stores @gpu scope
            __syncthreads();
            if (tid == 0) atomicAdd(&g_cnt[c], 1);
            __syncthreads();            // protect s_x
        }
    } else {
        // ============================ CONSUMER ============================
        const int b = blockIdx.x;
        unsigned long long wr[32];
        const unsigned long long* W =
            reinterpret_cast<const unsigned long long*>(w_hh) + (size_t)row * 64 + hf * 32;
        #pragma unroll
        for (int i = 0; i < 32; i++) wr[i] = W[i];
        const unsigned long long bias = (hf == 0) ? pack2(b_hh[row], 0.0f) : pack2(0.0f, 0.0f);

        if (tid < HID) s_h[tid] = 0.0f;
        float pool = 0.0f;
        float h_j  = 0.0f;

        const float* gi_b = g_gi + (size_t)b * G3;   // + t*BATCH*G3 per step

        wait_chunk(0, NPROD);
        if (tid < G3) s_gi[0][tid] = __ldcg(gi_b + tid);
        __syncthreads();

        int cnext = 1;
        for (int t = 0; t < TT; t++) {
            // ---- schedule next-step gi copy (async, one step of cover) ----
            if (t + 1 < TT) {
                if (t + 1 == cnext * NPROD) {
                    const int target = (TT - cnext * NPROD < NPROD) ? (TT - cnext * NPROD) : NPROD;
                    wait_chunk(cnext, target);
                    cnext++;
                }
                if (tid < G3 / 4) {
                    const float* src = gi_b + (size_t)(t + 1) * BATCH * G3 + tid * 4;
                    cp_async16((uint32_t)__cvta_generic_to_shared(&s_gi[(t + 1) & 1][tid * 4]), src);
                }
                asm volatile("cp.async.commit_group;" ::: "memory");
            }

            // ---- phase 1: partial dot: row `row`, K-half hf ----
            const ulonglong2* hp = reinterpret_cast<const ulonglong2*>(s_h + hf * 64);
            unsigned long long a0 = bias, a1 = pack2(0.0f, 0.0f);
            #pragma unroll
            for (int i = 0; i < 16; i++) {
                ulonglong2 v = hp[i];
                ffma2(a0, wr[2 * i],     v.x);
                ffma2(a1, wr[2 * i + 1], v.y);
            }
            float s0, s1, s2, s3;
            unpack2(a0, s0, s1);
            unpack2(a1, s2, s3);
            s_part[tid] = (s0 + s1) + (s2 + s3);

            // gi[t] copy (issued last step) must be landed before phase 2
            if (t == TT - 1) asm volatile("cp.async.wait_group 0;" ::: "memory");
            else             asm volatile("cp.async.wait_group 1;" ::: "memory");
            __syncthreads();

            // ---- phase 2: gates + h update (threads 0..127) ----
            if (tid < HID) {
                const float* gi_t = s_gi[t & 1];
                float gh_r = s_part[tid]       + s_part[tid + 384];
                float gh_z = s_part[tid + 128] + s_part[tid + 512];
                float gh_n = s_part[tid + 256] + s_part[tid + 640];
                float r = sigmoidf_(gi_t[tid] + gh_r);
                float z = sigmoidf_(gi_t[HID + tid] + gh_z);
                float cc = gi_t[2 * HID + tid] + r * gh_n;
                float n = 2.0f * sigmoidf_(2.0f * cc) - 1.0f;  // tanh(cc)
                h_j = n + z * (h_j - n);
                pool += h_j;
                s_h[tid] = h_j;
            }
            __syncthreads();
        }

        // ---- mean pool + projection ----
        if (tid < HID) s_pool[tid] = pool * (1.0f / (float)TT);
        __syncthreads();
        if (tid < 64) {
            float acc = b_proj[tid];
            const float* wp = w_proj + tid * HID;
            #pragma unroll 8
            for (int j = 0; j < HID; j++) acc += wp[j] * s_pool[j];
            out[b * 64 + tid] = acc;
        }
    }
}

extern "C" void kernel_launch(void* const* d_in, const int* in_sizes, int n_in,
                              void* d_out, int out_size) {
    const float* x      = (const float*)d_in[0];
    const float* w_ih   = (const float*)d_in[1];
    const float* w_hh   = (const float*)d_in[2];
    const float* b_ih   = (const float*)d_in[3];
    const float* b_hh   = (const float*)d_in[4];
    const float* w_proj = (const float*)d_in[5];
    const float* b_proj = (const float*)d_in[6];
    float* out = (float*)d_out;

    reset_kernel<<<1, 32>>>();
    gru_kernel<<<BATCH + NPROD, NTHR>>>(x, w_ih, w_hh, b_ih, b_hh, w_proj, b_proj, out);
}

// round 13
// speedup vs baseline: 1.3724x; 1.3724x over previous
#include <cuda_runtime.h>
#include <cstdint>

#define BATCH 64
#define TT    2048
#define HID   128
#define G3    384
#define NPROD 84
#define NTHR  384
#define NCH   ((TT + NPROD - 1) / NPROD)   // 25 chunks

// Scratch: gi[t][b][g] (201 MB) + per-chunk completion counters.
__device__ __align__(16) float g_gi[(size_t)TT * BATCH * G3];
__device__ int g_cnt[NCH];

__device__ __forceinline__ unsigned long long pack2(float lo, float hi) {
    unsigned long long r;
    asm("mov.b64 %0, {%1, %2};" : "=l"(r) : "f"(lo), "f"(hi));
    return r;
}
__device__ __forceinline__ void unpack2(unsigned long long v, float &lo, float &hi) {
    asm("mov.b64 {%0, %1}, %2;" : "=f"(lo), "=f"(hi) : "l"(v));
}
// Packed f32x2 FMA: d = a*b + d. 2x fp32 throughput on sm_103a.
__device__ __forceinline__ void ffma2(unsigned long long &d, unsigned long long a,
                                      unsigned long long b) {
    asm("fma.rn.f32x2 %0, %1, %2, %0;" : "+l"(d) : "l"(a), "l"(b));
}
__device__ __forceinline__ float sigmoidf_(float x) {
    return __fdividef(1.0f, 1.0f + __expf(-x));
}
__device__ __forceinline__ void cp_async16(uint32_t dst_smem, const void* src) {
    asm volatile("cp.async.cg.shared.global [%0], [%1], 16;"
                 :: "r"(dst_smem), "l"(src) : "memory");
}

// Every thread spins on a volatile read, then its own acquire-side fence
// (pairs with the producer's release fence through the observed atomic).
__device__ __forceinline__ void wait_chunk(int c, int target) {
    volatile int* p = (volatile int*)&g_cnt[c];
    while (*p < target) __nanosleep(64);
    __threadfence();
}

__global__ void reset_kernel() {
    int i = threadIdx.x;
    if (i < NCH) g_cnt[i] = 0;
}

__global__ void __launch_bounds__(NTHR, 1)
gru_kernel(const float* __restrict__ x,      // [B, T, 128]
           const float* __restrict__ w_ih,   // [384, 128]
           const float* __restrict__ w_hh,   // [384, 128]
           const float* __restrict__ b_ih,   // [384]
           const float* __restrict__ b_hh,   // [384]
           const float* __restrict__ w_proj, // [64, 128]
           const float* __restrict__ b_proj, // [64]
           float* __restrict__ out)          // [64, 64]
{
    __shared__ float s_x[BATCH * HID];                  // producer staging (32 KB)
    __shared__ float s_h[HID];
    __shared__ float s_gh[G3];
    __shared__ alignas(16) float s_gi[2][G3];           // gi double buffer
    __shared__ float s_pool[HID];

    const int tid = threadIdx.x;

    if (blockIdx.x >= BATCH) {
        // ============================ PRODUCER (R5-proven) ============================
        const int w = blockIdx.x - BATCH;
        unsigned long long wr[64];
        const unsigned long long* W =
            reinterpret_cast<const unsigned long long*>(w_ih) + (size_t)tid * 64;
        #pragma unroll
        for (int i = 0; i < 64; i++) wr[i] = W[i];
        const unsigned long long bias = pack2(b_ih[tid], 0.0f);

        for (int c = 0; c < NCH; c++) {
            const int t = c * NPROD + w;
            if (t >= TT) break;
            for (int idx = tid; idx < BATCH * HID; idx += NTHR)
                s_x[idx] = __ldcg(&x[(((size_t)(idx >> 7)) * TT + t) * HID + (idx & 127)]);
            __syncthreads();

            float* gout = g_gi + (size_t)t * BATCH * G3;
            for (int b = 0; b < BATCH; b++) {
                const ulonglong2* hx = reinterpret_cast<const ulonglong2*>(s_x + b * HID);
                unsigned long long a0 = bias, a1 = pack2(0.0f, 0.0f);
                #pragma unroll
                for (int i = 0; i < 32; i++) {
                    ulonglong2 v = hx[i];
                    ffma2(a0, wr[2 * i],     v.x);
                    ffma2(a1, wr[2 * i + 1], v.y);
                }
                float s0, s1, s2, s3;
                unpack2(a0, s0, s1);
                unpack2(a1, s2, s3);
                gout[b * G3 + tid] = (s0 + s1) + (s2 + s3);
            }
            __threadfence();            // release: order gi stores @gpu scope
            __syncthreads();
            if (tid == 0) atomicAdd(&g_cnt[c], 1);
            __syncthreads();            // protect s_x
        }
    } else {
        // ============================ CONSUMER ============================
        const int b = blockIdx.x;
        unsigned long long wr[64];
        const unsigned long long* W =
            reinterpret_cast<const unsigned long long*>(w_hh) + (size_t)tid * 64;
        #pragma unroll
        for (int i = 0; i < 64; i++) wr[i] = W[i];
        const unsigned long long bias = pack2(b_hh[tid], 0.0f);

        if (tid < HID) s_h[tid] = 0.0f;
        float pool = 0.0f;
        float h_j  = 0.0f;

        const float* gi_b = g_gi + (size_t)b * G3;   // + t*BATCH*G3 per step

        wait_chunk(0, NPROD);
        if (tid < G3) s_gi[0][tid] = __ldcg(gi_b + tid);
        __syncthreads();

        int cnext = 1;
        for (int t = 0; t < TT; t++) {
            // ---- schedule next-step gi copy (async-proxy: cannot be sunk) ----
            if (t + 1 < TT) {
                if (t + 1 == cnext * NPROD) {
                    const int target = (TT - cnext * NPROD < NPROD) ? (TT - cnext * NPROD) : NPROD;
                    wait_chunk(cnext, target);
                    cnext++;
                }
                if (tid < G3 / 4) {
                    const float* src = gi_b + (size_t)(t + 1) * BATCH * G3 + tid * 4;
                    cp_async16((uint32_t)__cvta_generic_to_shared(&s_gi[(t + 1) & 1][tid * 4]), src);
                }
                asm volatile("cp.async.commit_group;" ::: "memory");
            }

            // ---- phase 1: gh[g] = w_hh[g,:] . h + b_hh[g]  (4 accumulators) ----
            const ulonglong2* hp = reinterpret_cast<const ulonglong2*>(s_h);
            unsigned long long a0 = bias, a1 = pack2(0.0f, 0.0f);
            unsigned long long a2 = pack2(0.0f, 0.0f), a3 = pack2(0.0f, 0.0f);
            #pragma unroll
            for (int i = 0; i < 16; i++) {
                ulonglong2 v0 = hp[2 * i];
                ulonglong2 v1 = hp[2 * i + 1];
                ffma2(a0, wr[4 * i],     v0.x);
                ffma2(a1, wr[4 * i + 1], v0.y);
                ffma2(a2, wr[4 * i + 2], v1.x);
                ffma2(a3, wr[4 * i + 3], v1.y);
            }
            float s0, s1, s2, s3, s4, s5, s6, s7;
            unpack2(a0, s0, s1);
            unpack2(a1, s2, s3);
            unpack2(a2, s4, s5);
            unpack2(a3, s6, s7);
            s_gh[tid] = ((s0 + s1) + (s2 + s3)) + ((s4 + s5) + (s6 + s7));

            // gi[t] copy (issued last step) must have landed before phase 2
            if (t == TT - 1) asm volatile("cp.async.wait_group 0;" ::: "memory");
            else             asm volatile("cp.async.wait_group 1;" ::: "memory");
            __syncthreads();

            // ---- phase 2: gates + h update (threads 0..127) ----
            if (tid < HID) {
                const float* gi_t = s_gi[t & 1];
                float r = sigmoidf_(gi_t[tid] + s_gh[tid]);
                float z = sigmoidf_(gi_t[HID + tid] + s_gh[HID + tid]);
                float cc = gi_t[2 * HID + tid] + r * s_gh[2 * HID + tid];
                float n = 2.0f * sigmoidf_(2.0f * cc) - 1.0f;  // tanh(cc)
                h_j = n + z * (h_j - n);
                pool += h_j;
                s_h[tid] = h_j;
            }
            __syncthreads();
        }

        // ---- mean pool + projection ----
        if (tid < HID) s_pool[tid] = pool * (1.0f / (float)TT);
        __syncthreads();
        if (tid < 64) {
            float acc = b_proj[tid];
            const float* wp = w_proj + tid * HID;
            #pragma unroll 8
            for (int j = 0; j < HID; j++) acc += wp[j] * s_pool[j];
            out[b * 64 + tid] = acc;
        }
    }
}

extern "C" void kernel_launch(void* const* d_in, const int* in_sizes, int n_in,
                              void* d_out, int out_size) {
    const float* x      = (const float*)d_in[0];
    const float* w_ih   = (const float*)d_in[1];
    const float* w_hh   = (const float*)d_in[2];
    const float* b_ih   = (const float*)d_in[3];
    const float* b_hh   = (const float*)d_in[4];
    const float* w_proj = (const float*)d_in[5];
    const float* b_proj = (const float*)d_in[6];
    float* out = (float*)d_out;

    reset_kernel<<<1, 32>>>();
    gru_kernel<<<BATCH + NPROD, NTHR>>>(x, w_ih, w_hh, b_ih, b_hh, w_proj, b_proj, out);
}

// round 14
// speedup vs baseline: 1.4766x; 1.0759x over previous
#include <cuda_runtime.h>
#include <cstdint>

#define BATCH 64
#define TT    2048
#define HID   128
#define G3    384
#define NPROD 84
#define NTHR  384
#define NCH   ((TT + NPROD - 1) / NPROD)   // 25 chunks

// Scratch: gi[t][b][g] (201 MB) + per-chunk completion counters.
__device__ __align__(16) float g_gi[(size_t)TT * BATCH * G3];
__device__ int g_cnt[NCH];

__device__ __forceinline__ unsigned long long pack2(float lo, float hi) {
    unsigned long long r;
    asm("mov.b64 %0, {%1, %2};" : "=l"(r) : "f"(lo), "f"(hi));
    return r;
}
__device__ __forceinline__ void unpack2(unsigned long long v, float &lo, float &hi) {
    asm("mov.b64 {%0, %1}, %2;" : "=f"(lo), "=f"(hi) : "l"(v));
}
// Packed f32x2 FMA: d = a*b + d. 2x fp32 throughput on sm_103a.
__device__ __forceinline__ void ffma2(unsigned long long &d, unsigned long long a,
                                      unsigned long long b) {
    asm("fma.rn.f32x2 %0, %1, %2, %0;" : "+l"(d) : "l"(a), "l"(b));
}
// Single-MUFU tanh (sm_75+). abs err ~1e-4 — fine for 1e-3 threshold.
__device__ __forceinline__ float tanh_apx(float x) {
    float y;
    asm("tanh.approx.f32 %0, %1;" : "=f"(y) : "f"(x));
    return y;
}
__device__ __forceinline__ float sigmoid_apx(float x) {
    return fmaf(0.5f, tanh_apx(0.5f * x), 0.5f);
}
__device__ __forceinline__ void cp_async16(uint32_t dst_smem, const void* src) {
    asm volatile("cp.async.cg.shared.global [%0], [%1], 16;"
                 :: "r"(dst_smem), "l"(src) : "memory");
}
// Every thread spins on a volatile read, then its own acquire-side fence.
__device__ __forceinline__ void wait_chunk(int c, int target) {
    volatile int* p = (volatile int*)&g_cnt[c];
    while (*p < target) __nanosleep(64);
    __threadfence();
}

__global__ void reset_kernel() {
    int i = threadIdx.x;
    if (i < NCH) g_cnt[i] = 0;
}

__global__ void __launch_bounds__(NTHR, 1)
gru_kernel(const float* __restrict__ x,      // [B, T, 128]
           const float* __restrict__ w_ih,   // [384, 128]
           const float* __restrict__ w_hh,   // [384, 128]
           const float* __restrict__ b_ih,   // [384]
           const float* __restrict__ b_hh,   // [384]
           const float* __restrict__ w_proj, // [64, 128]
           const float* __restrict__ b_proj, // [64]
           float* __restrict__ out)          // [64, 64]
{
    __shared__ float s_x[BATCH * HID];                  // producer staging (32 KB)
    __shared__ float s_h[HID];
    __shared__ float s_gh[G3];
    __shared__ alignas(16) float s_gi[3][G3];           // gi TRIPLE buffer (2-step cover)
    __shared__ float s_pool[HID];

    const int tid = threadIdx.x;

    if (blockIdx.x >= BATCH) {
        // ============================ PRODUCER (R5/R13-proven) ============================
        const int w = blockIdx.x - BATCH;
        unsigned long long wr[64];
        const unsigned long long* W =
            reinterpret_cast<const unsigned long long*>(w_ih) + (size_t)tid * 64;
        #pragma unroll
        for (int i = 0; i < 64; i++) wr[i] = W[i];
        const unsigned long long bias = pack2(b_ih[tid], 0.0f);

        for (int c = 0; c < NCH; c++) {
            const int t = c * NPROD + w;
            if (t >= TT) break;
            for (int idx = tid; idx < BATCH * HID; idx += NTHR)
                s_x[idx] = __ldcg(&x[(((size_t)(idx >> 7)) * TT + t) * HID + (idx & 127)]);
            __syncthreads();

            float* gout = g_gi + (size_t)t * BATCH * G3;
            for (int b = 0; b < BATCH; b++) {
                const ulonglong2* hx = reinterpret_cast<const ulonglong2*>(s_x + b * HID);
                unsigned long long a0 = bias, a1 = pack2(0.0f, 0.0f);
                #pragma unroll
                for (int i = 0; i < 32; i++) {
                    ulonglong2 v = hx[i];
                    ffma2(a0, wr[2 * i],     v.x);
                    ffma2(a1, wr[2 * i + 1], v.y);
                }
                float s0, s1, s2, s3;
                unpack2(a0, s0, s1);
                unpack2(a1, s2, s3);
                gout[b * G3 + tid] = (s0 + s1) + (s2 + s3);
            }
            __threadfence();            // release: order gi stores @gpu scope
            __syncthreads();
            if (tid == 0) atomicAdd(&g_cnt[c], 1);
            __syncthreads();            // protect s_x
        }
    } else {
        // ============================ CONSUMER ============================
        const int b = blockIdx.x;
        unsigned long long wr[64];
        const unsigned long long* W =
            reinterpret_cast<const unsigned long long*>(w_hh) + (size_t)tid * 64;
        #pragma unroll
        for (int i = 0; i < 64; i++) wr[i] = W[i];
        const unsigned long long bias = pack2(b_hh[tid], 0.0f);

        if (tid < HID) s_h[tid] = 0.0f;
        float pool = 0.0f;
        float h_j  = 0.0f;

        const float* gi_b = g_gi + (size_t)b * G3;   // + t*BATCH*G3 per step

        // Prime: gi[0] synchronous, gi[1] async (group committed). NPROD > 2,
        // so t = 0..2 all live in chunk 0.
        wait_chunk(0, NPROD);
        if (tid < G3) s_gi[0][tid] = __ldcg(gi_b + tid);
        if (tid < G3 / 4)
            cp_async16((uint32_t)__cvta_generic_to_shared(&s_gi[1][tid * 4]),
                       gi_b + (size_t)1 * BATCH * G3 + tid * 4);
        asm volatile("cp.async.commit_group;" ::: "memory");
        __syncthreads();

        int cnext = 1;
        for (int t = 0; t < TT; t++) {
            // ---- schedule gi copy for t+2 (2 steps of cover); one group/step ----
            if (t + 2 < TT) {
                if (t + 2 == cnext * NPROD) {
                    const int target = (TT - cnext * NPROD < NPROD) ? (TT - cnext * NPROD) : NPROD;
                    wait_chunk(cnext, target);
                    cnext++;
                }
                if (tid < G3 / 4) {
                    const float* src = gi_b + (size_t)(t + 2) * BATCH * G3 + tid * 4;
                    cp_async16((uint32_t)__cvta_generic_to_shared(&s_gi[(t + 2) % 3][tid * 4]), src);
                }
            }
            asm volatile("cp.async.commit_group;" ::: "memory");   // empty group OK

            // ---- phase 1: gh[g] = w_hh[g,:] . h + b_hh[g]  (4 accumulators) ----
            const ulonglong2* hp = reinterpret_cast<const ulonglong2*>(s_h);
            unsigned long long a0 = bias, a1 = pack2(0.0f, 0.0f);
            unsigned long long a2 = pack2(0.0f, 0.0f), a3 = pack2(0.0f, 0.0f);
            #pragma unroll
            for (int i = 0; i < 16; i++) {
                ulonglong2 v0 = hp[2 * i];
                ulonglong2 v1 = hp[2 * i + 1];
                ffma2(a0, wr[4 * i],     v0.x);
                ffma2(a1, wr[4 * i + 1], v0.y);
                ffma2(a2, wr[4 * i + 2], v1.x);
                ffma2(a3, wr[4 * i + 3], v1.y);
            }
            float s0, s1, s2, s3, s4, s5, s6, s7;
            unpack2(a0, s0, s1);
            unpack2(a1, s2, s3);
            unpack2(a2, s4, s5);
            unpack2(a3, s6, s7);
            s_gh[tid] = ((s0 + s1) + (s2 + s3)) + ((s4 + s5) + (s6 + s7));

            // exactly one group committed per step -> 2 back = group covering gi[t]
            asm volatile("cp.async.wait_group 2;" ::: "memory");
            __syncthreads();

            // ---- phase 2: gates + h update (threads 0..127), tanh.approx ----
            if (tid < HID) {
                const float* gi_t = s_gi[t % 3];
                float r  = sigmoid_apx(gi_t[tid] + s_gh[tid]);
                float z  = sigmoid_apx(gi_t[HID + tid] + s_gh[HID + tid]);
                float cc = gi_t[2 * HID + tid] + r * s_gh[2 * HID + tid];
                float n  = tanh_apx(cc);
                h_j = n + z * (h_j - n);
                pool += h_j;
                s_h[tid] = h_j;
            }
            __syncthreads();
        }

        // ---- mean pool + projection ----
        if (tid < HID) s_pool[tid] = pool * (1.0f / (float)TT);
        __syncthreads();
        if (tid < 64) {
            float acc = b_proj[tid];
            const float* wp = w_proj + tid * HID;
            #pragma unroll 8
            for (int j = 0; j < HID; j++) acc += wp[j] * s_pool[j];
            out[b * 64 + tid] = acc;
        }
    }
}

extern "C" void kernel_launch(void* const* d_in, const int* in_sizes, int n_in,
                              void* d_out, int out_size) {
    const float* x      = (const float*)d_in[0];
    const float* w_ih   = (const float*)d_in[1];
    const float* w_hh   = (const float*)d_in[2];
    const float* b_ih   = (const float*)d_in[3];
    const float* b_hh   = (const float*)d_in[4];
    const float* w_proj = (const float*)d_in[5];
    const float* b_proj = (const float*)d_in[6];
    float* out = (float*)d_out;

    reset_kernel<<<1, 32>>>();
    gru_kernel<<<BATCH + NPROD, NTHR>>>(x, w_ih, w_hh, b_ih, b_hh, w_proj, b_proj, out);
}